// round 8
// baseline (speedup 1.0000x reference)
#include <cuda_runtime.h>
#include <cuda_bf16.h>
#include <cstdint>

#define BB 512
#define DD 256
#define S_SCALE 30.0f
#define MARGIN 0.2f
#define EXPC 43.2808512f          // 30 * log2(e)

// -------- device scratch --------
__device__ char  g_xq[BB * DD];      // int8-quantized normalized X
__device__ float g_xscale[BB];       // per-row scale: maxv*inv_norm/127
__device__ float g_sumexp[BB];
__device__ float g_cost[BB];
__device__ int   g_targets[BB];

// ---------------- helpers ----------------
__device__ __forceinline__ uint32_t smem_u32(const void* p) {
    uint32_t a;
    asm("{ .reg .u64 t; cvta.to.shared.u64 t, %1; cvt.u32.u64 %0, t; }"
        : "=r"(a) : "l"(p));
    return a;
}

#define CP16F(sa, ga) \
    asm volatile("cp.async.cg.shared.global [%0], [%1], 16;" \
                 :: "r"(sa), "l"(ga) : "memory")
#define CP_COMMIT() asm volatile("cp.async.commit_group;" ::: "memory")
#define CP_WAIT1()  asm volatile("cp.async.wait_group 1;" ::: "memory")
#define CP_WAIT0()  asm volatile("cp.async.wait_group 0;" ::: "memory")

#define LDSM4(r0, r1, r2, r3, addr) \
    asm volatile("ldmatrix.sync.aligned.m8n8.x4.shared.b16 {%0,%1,%2,%3}, [%4];" \
                 : "=r"(r0), "=r"(r1), "=r"(r2), "=r"(r3) : "r"(addr))

__device__ __forceinline__ void imma16832(int* d, const uint32_t* a,
                                          uint32_t b0, uint32_t b1) {
    asm volatile(
        "mma.sync.aligned.m16n8k32.row.col.s32.s8.s8.s32 "
        "{%0,%1,%2,%3}, {%4,%5,%6,%7}, {%8,%9}, {%0,%1,%2,%3};\n"
        : "+r"(d[0]), "+r"(d[1]), "+r"(d[2]), "+r"(d[3])
        : "r"(a[0]), "r"(a[1]), "r"(a[2]), "r"(a[3]), "r"(b0), "r"(b1));
}

// pack 4 floats -> 4 int8 (values guaranteed within +-127)
__device__ __forceinline__ uint32_t q4(float4 f, float qs) {
    int q0 = __float2int_rn(f.x * qs) & 255;
    int q1 = __float2int_rn(f.y * qs) & 255;
    int q2 = __float2int_rn(f.z * qs) & 255;
    int q3 = __float2int_rn(f.w * qs) & 255;
    return (uint32_t)(q0 | (q1 << 8) | (q2 << 16) | (q3 << 24));
}

// Blocked-atom SW128 tile for int8: 128 rows x 256 int8 (16 chunks of 16B/row).
// atom = 8 rows x 128B; atom idx = (r>>3) + (cc>>3)*16.
__device__ __forceinline__ uint32_t tile_off(int r, int cc) {
    return (uint32_t)(((r >> 3) + (cc >> 3) * 16) * 1024
                    + (r & 7) * 128 + ((((cc & 7) * 16) ^ ((r & 7) << 4))));
}

// ---------------------------------------------------------
// prep + X normalize/quantize (merged).
__global__ void prep_norm_kernel(const float* __restrict__ in,
                                 const int* __restrict__ t32) {
    if (blockIdx.x == 0) {
        __shared__ int flag;
        int i = threadIdx.x;  // 256 threads
        if (i == 0) flag = 0;
        __syncthreads();
        if (t32[2 * i + 1] != 0) flag = 1;   // odd words of first 512
        __syncthreads();
#pragma unroll
        for (int k = 0; k < 2; k++) {
            int j = i + 256 * k;
            g_targets[j] = flag ? t32[j] : (int)((const long long*)t32)[j];
            g_sumexp[j] = 0.0f;
        }
    }
    int row = blockIdx.x * 8 + (threadIdx.x >> 5);
    int lane = threadIdx.x & 31;
    const float4* p = (const float4*)(in + (size_t)row * DD);
    float4 v0 = p[lane];
    float4 v1 = p[lane + 32];
    float ss = v0.x * v0.x + v0.y * v0.y + v0.z * v0.z + v0.w * v0.w
             + v1.x * v1.x + v1.y * v1.y + v1.z * v1.z + v1.w * v1.w;
    float mv = fmaxf(fmaxf(fmaxf(fabsf(v0.x), fabsf(v0.y)),
                           fmaxf(fabsf(v0.z), fabsf(v0.w))),
                     fmaxf(fmaxf(fabsf(v1.x), fabsf(v1.y)),
                           fmaxf(fabsf(v1.z), fabsf(v1.w))));
#pragma unroll
    for (int o = 16; o; o >>= 1) {
        ss += __shfl_xor_sync(0xffffffffu, ss, o);
        mv = fmaxf(mv, __shfl_xor_sync(0xffffffffu, mv, o));
    }
    float qs = 127.0f / mv;
    uint32_t* q = (uint32_t*)(g_xq + (size_t)row * DD);
    q[lane]      = q4(v0, qs);
    q[lane + 32] = q4(v1, qs);
    if (lane == 0) g_xscale[row] = mv * rsqrtf(ss) * (1.0f / 127.0f);
}

// ---------------------------------------------------------
// exact fp32 target cosine (margin term no longer mimics GEMM numerics)
__global__ void cost_kernel(const float* __restrict__ W,
                            const float* __restrict__ X) {
    int b = blockIdx.x * 8 + (threadIdx.x >> 5);
    int lane = threadIdx.x & 31;
    int c = g_targets[b];
    const float4* wr = (const float4*)(W + (size_t)c * DD);
    const float4* xr = (const float4*)(X + (size_t)b * DD);
    float dxx = 0.f, dww = 0.f, dxw = 0.f;
#pragma unroll
    for (int h = 0; h < 2; h++) {
        float4 w = wr[lane + 32 * h];
        float4 x = xr[lane + 32 * h];
        dww += w.x * w.x + w.y * w.y + w.z * w.z + w.w * w.w;
        dxx += x.x * x.x + x.y * x.y + x.z * x.z + x.w * x.w;
        dxw += w.x * x.x + w.y * x.y + w.z * x.z + w.w * x.w;
    }
#pragma unroll
    for (int o = 16; o; o >>= 1) {
        dxx += __shfl_xor_sync(0xffffffffu, dxx, o);
        dww += __shfl_xor_sync(0xffffffffu, dww, o);
        dxw += __shfl_xor_sync(0xffffffffu, dxw, o);
    }
    if (lane == 0) g_cost[b] = dxw * rsqrtf(dxx * dww);
}

// ---------------------------------------------------------
// INT8 GEMM + exp-sum, occupancy 2.
// CTA: 128-class tile; W fp32 read once, normalized+quantized -> int8 SW128
// (32KB) + per-class scale (smem). X int8 in 2x32KB double buffer (cp.async).
// mma.sync m16n8k32.s8; cosine = acc * sx[row] * sw[col] in epilogue.
#define SM_W    0
#define SM_SWS  32768                 // 128 floats
#define SM_X0   33792                 // 1024-aligned
#define SM_X1   (33792 + 32768)
#define SM_TOTAL (33792 + 2 * 32768)

__global__ __launch_bounds__(256, 2) void gemm_sumexp_kernel(
        const float* __restrict__ W, int C) {
    extern __shared__ char smem[];
    const uint32_t sb = smem_u32(smem);
    float* sws = (float*)(smem + SM_SWS);
    const int tid = threadIdx.x, wid = tid >> 5, lane = tid & 31;
    const int cbase = blockIdx.x * 128;
    const char* xsrc = (const char*)g_xq;

    // prefetch X blocks 0,1 (async): 2048 16B-chunks per block, 8 per thread
#pragma unroll
    for (int it = 0; it < 8; it++) {
        int i = tid + 256 * it, r = i >> 4, cc = i & 15;
        CP16F(sb + SM_X0 + tile_off(r, cc), xsrc + (size_t)r * 256 + cc * 16);
    }
    CP_COMMIT();
#pragma unroll
    for (int it = 0; it < 8; it++) {
        int i = tid + 256 * it, r = i >> 4, cc = i & 15;
        CP16F(sb + SM_X1 + tile_off(r, cc),
              xsrc + (size_t)(128 + r) * 256 + cc * 16);
    }
    CP_COMMIT();

    // fused W normalize+quantize: 2 threads per row, 2-pass via L1
    {
        int r = tid >> 1, h = tid & 1;
        int cg = cbase + r;
        bool ok = (cg < C);
        const float4* wrow =
            (const float4*)(W + (size_t)(ok ? cg : cbase) * DD) + h * 32;
        float ss = 0.f, mv = 0.f;
#pragma unroll
        for (int i = 0; i < 32; i++) {
            float4 v = wrow[i];
            ss += v.x * v.x + v.y * v.y + v.z * v.z + v.w * v.w;
            mv = fmaxf(mv, fmaxf(fmaxf(fabsf(v.x), fabsf(v.y)),
                                 fmaxf(fabsf(v.z), fabsf(v.w))));
        }
        ss += __shfl_xor_sync(0xffffffffu, ss, 1);
        mv = fmaxf(mv, __shfl_xor_sync(0xffffffffu, mv, 1));
        float qs = ok ? 127.0f / mv : 0.0f;
#pragma unroll
        for (int k = 0; k < 8; k++) {
            uint4 u;
            u.x = q4(wrow[4 * k + 0], qs);
            u.y = q4(wrow[4 * k + 1], qs);
            u.z = q4(wrow[4 * k + 2], qs);
            u.w = q4(wrow[4 * k + 3], qs);
            *(uint4*)(smem + SM_W + tile_off(r, h * 8 + k)) = u;
        }
        if (h == 0)
            sws[r] = ok ? mv * rsqrtf(ss) * (1.0f / 127.0f) : 0.0f;
    }
    CP_WAIT1();        // X0 resident; X1 in flight
    __syncthreads();

    const int wm = wid & 3, wn = wid >> 2;
    const int m0 = wm * 32, n0 = wn * 64;
    const int g = lane >> 2, t = lane & 3;
    const int a_rl   = ((lane >> 3) & 1) * 8 + (lane & 7);
    const int a_cchi = (lane >> 4) & 1;
    const int b_rl   = ((lane >> 4) & 1) * 8 + (lane & 7);
    const int b_cchi = (lane >> 3) & 1;
    const uint32_t wa = sb + SM_W;

    // hoist per-column W scales (same for all 4 batch blocks)
    float swv[8][2];
#pragma unroll
    for (int j = 0; j < 8; j++) {
        int c0 = n0 + 8 * j + 2 * t;
        swv[j][0] = sws[c0];
        swv[j][1] = sws[c0 + 1];
    }

    for (int b = 0; b < 4; b++) {
        const uint32_t xa = sb + ((b & 1) ? SM_X1 : SM_X0);

        int acc[2][8][4];
#pragma unroll
        for (int i = 0; i < 2; i++)
#pragma unroll
            for (int j = 0; j < 8; j++)
#pragma unroll
                for (int q = 0; q < 4; q++) acc[i][j][q] = 0;

#pragma unroll
        for (int s = 0; s < 8; s++) {
            uint32_t afr[2][4];
#pragma unroll
            for (int i = 0; i < 2; i++) {
                LDSM4(afr[i][0], afr[i][1], afr[i][2], afr[i][3],
                      xa + tile_off(m0 + 16 * i + a_rl, 2 * s + a_cchi));
            }
            uint32_t bfr[4][4];
#pragma unroll
            for (int j4 = 0; j4 < 4; j4++) {
                LDSM4(bfr[j4][0], bfr[j4][1], bfr[j4][2], bfr[j4][3],
                      wa + tile_off(n0 + 16 * j4 + b_rl, 2 * s + b_cchi));
            }
#pragma unroll
            for (int j = 0; j < 8; j++) {
                uint32_t b0 = bfr[j >> 1][(j & 1) * 2];
                uint32_t b1 = bfr[j >> 1][(j & 1) * 2 + 1];
                imma16832(acc[0][j], afr[0], b0, b1);
                imma16832(acc[1][j], afr[1], b0, b1);
            }
        }

        // epilogue: scale to cosine, exp2, per-row reduce
        float sx[2][2];
#pragma unroll
        for (int i = 0; i < 2; i++) {
            sx[i][0] = g_xscale[b * 128 + m0 + 16 * i + g];
            sx[i][1] = g_xscale[b * 128 + m0 + 16 * i + g + 8];
        }
        float rs[4] = {0.f, 0.f, 0.f, 0.f};
#pragma unroll
        for (int i = 0; i < 2; i++)
#pragma unroll
            for (int j = 0; j < 8; j++) {
                float s00 = sx[i][0] * swv[j][0], s01 = sx[i][0] * swv[j][1];
                float s10 = sx[i][1] * swv[j][0], s11 = sx[i][1] * swv[j][1];
                rs[2 * i] +=
                    exp2f(fmaf(EXPC * s00, (float)acc[i][j][0], -EXPC))
                  + exp2f(fmaf(EXPC * s01, (float)acc[i][j][1], -EXPC));
                rs[2 * i + 1] +=
                    exp2f(fmaf(EXPC * s10, (float)acc[i][j][2], -EXPC))
                  + exp2f(fmaf(EXPC * s11, (float)acc[i][j][3], -EXPC));
            }
#pragma unroll
        for (int q = 0; q < 4; q++) {
            rs[q] += __shfl_xor_sync(0xffffffffu, rs[q], 1);
            rs[q] += __shfl_xor_sync(0xffffffffu, rs[q], 2);
        }
        if ((lane & 3) == 0) {
            int rbase = b * 128 + m0 + g;
#pragma unroll
            for (int q = 0; q < 4; q++)
                atomicAdd(&g_sumexp[rbase + 8 * q], rs[q]);
        }

        __syncthreads();   // everyone done reading buf[b&1]
        if (b < 2) {
            uint32_t dst = sb + ((b & 1) ? SM_X1 : SM_X0);
#pragma unroll
            for (int it = 0; it < 8; it++) {
                int i = tid + 256 * it, r = i >> 4, cc = i & 15;
                CP16F(dst + tile_off(r, cc),
                      xsrc + (size_t)((b + 2) * 128 + r) * 256 + cc * 16);
            }
            CP_COMMIT();
            CP_WAIT1();
        } else if (b == 2) {
            CP_WAIT0();
        }
        __syncthreads();
    }
}

// ---------------------------------------------------------
// finalize: pad removal, margin correction (exact cosine), lse, mean
__global__ void finalize_kernel(float* __restrict__ out, int npad) {
    __shared__ double sd[BB];
    int b = threadIdx.x;
    float ct = g_cost[b];
    float lt = S_SCALE * (ct - MARGIN);
    float s = g_sumexp[b] - (float)npad * expf(-30.0f)
            + __expf(lt - 30.0f) - __expf(S_SCALE * ct - 30.0f);
    float nll = 30.0f + logf(s) - lt;
    sd[b] = (double)nll;
    __syncthreads();
    for (int o = 256; o; o >>= 1) {
        if (b < o) sd[b] += sd[b + o];
        __syncthreads();
    }
    if (b == 0) out[0] = (float)(sd[0] / (double)BB);
}

// ---------------------------------------------------------
extern "C" void kernel_launch(void* const* d_in, const int* in_sizes, int n_in,
                              void* d_out, int out_size) {
    const float* inputs  = (const float*)d_in[0];
    const float* weight  = (const float*)d_in[1];
    const int*   targets = (const int*)d_in[2];
    float* out = (float*)d_out;

    int C = in_sizes[1] / DD;
    int gridC = (C + 127) / 128;
    int npad = gridC * 128 - C;

    cudaFuncSetAttribute(gemm_sumexp_kernel,
                         cudaFuncAttributeMaxDynamicSharedMemorySize, SM_TOTAL);

    prep_norm_kernel<<<BB / 8, 256>>>(inputs, targets);
    cost_kernel<<<BB / 8, 256>>>(weight, inputs);
    gemm_sumexp_kernel<<<gridC, 256, SM_TOTAL>>>(weight, C);
    finalize_kernel<<<1, BB>>>(out, npad);
}

// round 9
// speedup vs baseline: 2.0080x; 2.0080x over previous
#include <cuda_runtime.h>
#include <cuda_fp16.h>
#include <cstdint>

#define BB 512
#define DD 256
#define S_SCALE 30.0f
#define MARGIN 0.2f
#define EXPC 43.2808512f          // 30 * log2(e)

// -------- device scratch --------
__device__ __half g_xn[BB * DD];     // normalized X, fp16
__device__ float g_sumexp[BB];
__device__ float g_cost[BB];
__device__ int   g_targets[BB];

// ---------------- helpers ----------------
__device__ __forceinline__ uint32_t smem_u32(const void* p) {
    uint32_t a;
    asm("{ .reg .u64 t; cvta.to.shared.u64 t, %1; cvt.u32.u64 %0, t; }"
        : "=r"(a) : "l"(p));
    return a;
}

#define CP16F(sa, ga) \
    asm volatile("cp.async.cg.shared.global [%0], [%1], 16;" \
                 :: "r"(sa), "l"(ga) : "memory")
#define CP_COMMIT() asm volatile("cp.async.commit_group;" ::: "memory")
#define CP_WAIT1()  asm volatile("cp.async.wait_group 1;" ::: "memory")
#define CP_WAIT0()  asm volatile("cp.async.wait_group 0;" ::: "memory")

#define LDSM4(r0, r1, r2, r3, addr) \
    asm volatile("ldmatrix.sync.aligned.m8n8.x4.shared.b16 {%0,%1,%2,%3}, [%4];" \
                 : "=r"(r0), "=r"(r1), "=r"(r2), "=r"(r3) : "r"(addr))

// fp16-accumulator HMMA (full-rate variant)
__device__ __forceinline__ void mma16816h(uint32_t* d, const uint32_t* a,
                                          uint32_t b0, uint32_t b1) {
    asm volatile(
        "mma.sync.aligned.m16n8k16.row.col.f16.f16.f16.f16 "
        "{%0,%1}, {%2,%3,%4,%5}, {%6,%7}, {%0,%1};\n"
        : "+r"(d[0]), "+r"(d[1])
        : "r"(a[0]), "r"(a[1]), "r"(a[2]), "r"(a[3]), "r"(b0), "r"(b1));
}

__device__ __forceinline__ uint32_t pack_h2(float x, float y) {
    __half2 h = __floats2half2_rn(x, y);
    return *reinterpret_cast<uint32_t*>(&h);
}
__device__ __forceinline__ float2 h2_to_f2(uint32_t u) {
    __half2 h;
    *reinterpret_cast<uint32_t*>(&h) = u;
    return __half22float2(h);
}

// SW128 blocked-atom tile: 128 rows x 256 fp16 (32 chunks of 16B per row).
__device__ __forceinline__ uint32_t tile_off(int r, int cc) {
    return (uint32_t)(((r >> 3) + (cc >> 3) * 16) * 1024
                    + (r & 7) * 128 + ((((cc & 7) * 16) ^ ((r & 7) << 4))));
}

// ---------------------------------------------------------
// prep + X normalize (merged).
__global__ void prep_norm_kernel(const float* __restrict__ in,
                                 const int* __restrict__ t32) {
    if (blockIdx.x == 0) {
        __shared__ int flag;
        int i = threadIdx.x;  // 256 threads
        if (i == 0) flag = 0;
        __syncthreads();
        if (t32[2 * i + 1] != 0) flag = 1;   // odd words of first 512
        __syncthreads();
#pragma unroll
        for (int k = 0; k < 2; k++) {
            int j = i + 256 * k;
            g_targets[j] = flag ? t32[j] : (int)((const long long*)t32)[j];
            g_sumexp[j] = 0.0f;
        }
    }
    int row = blockIdx.x * 8 + (threadIdx.x >> 5);
    int lane = threadIdx.x & 31;
    const float4* p = (const float4*)(in + (size_t)row * DD);
    float4 v0 = p[lane];
    float4 v1 = p[lane + 32];
    float s = v0.x * v0.x + v0.y * v0.y + v0.z * v0.z + v0.w * v0.w
            + v1.x * v1.x + v1.y * v1.y + v1.z * v1.z + v1.w * v1.w;
#pragma unroll
    for (int o = 16; o; o >>= 1) s += __shfl_xor_sync(0xffffffffu, s, o);
    float inv = rsqrtf(s);
    unsigned* q = (unsigned*)(g_xn + (size_t)row * DD);
    q[2 * lane + 0]        = pack_h2(v0.x * inv, v0.y * inv);
    q[2 * lane + 1]        = pack_h2(v0.z * inv, v0.w * inv);
    q[2 * (lane + 32) + 0] = pack_h2(v1.x * inv, v1.y * inv);
    q[2 * (lane + 32) + 1] = pack_h2(v1.z * inv, v1.w * inv);
}

// ---------------------------------------------------------
// exact fp32 target cosine
__global__ void cost_kernel(const float* __restrict__ W,
                            const float* __restrict__ X) {
    int b = blockIdx.x * 8 + (threadIdx.x >> 5);
    int lane = threadIdx.x & 31;
    int c = g_targets[b];
    const float4* wr = (const float4*)(W + (size_t)c * DD);
    const float4* xr = (const float4*)(X + (size_t)b * DD);
    float dxx = 0.f, dww = 0.f, dxw = 0.f;
#pragma unroll
    for (int h = 0; h < 2; h++) {
        float4 w = wr[lane + 32 * h];
        float4 x = xr[lane + 32 * h];
        dww += w.x * w.x + w.y * w.y + w.z * w.z + w.w * w.w;
        dxx += x.x * x.x + x.y * x.y + x.z * x.z + x.w * x.w;
        dxw += w.x * x.x + w.y * x.y + w.z * x.z + w.w * x.w;
    }
#pragma unroll
    for (int o = 16; o; o >>= 1) {
        dxx += __shfl_xor_sync(0xffffffffu, dxx, o);
        dww += __shfl_xor_sync(0xffffffffu, dww, o);
        dxw += __shfl_xor_sync(0xffffffffu, dxw, o);
    }
    if (lane == 0) g_cost[b] = dxw * rsqrtf(dxx * dww);
}

// ---------------------------------------------------------
// GEMM + exp-sum with fused W normalization. fp16 inputs, fp16 accumulators.
#define SM_W   0
#define SM_X0  65536
#define SM_X1  131072
#define SM_TOTAL 196608

__global__ __launch_bounds__(256, 1) void gemm_sumexp_kernel(
        const float* __restrict__ W, int C) {
    extern __shared__ char smem[];
    const uint32_t sb = smem_u32(smem);
    const int tid = threadIdx.x, wid = tid >> 5, lane = tid & 31;
    const int cbase = blockIdx.x * 128;
    const char* xsrc = (const char*)g_xn;

    // prefetch X blocks 0,1 (async)
#pragma unroll
    for (int it = 0; it < 16; it++) {
        int i = tid + 256 * it, r = i >> 5, cc = i & 31;
        CP16F(sb + SM_X0 + tile_off(r, cc), xsrc + ((size_t)r * 32 + cc) * 16);
    }
    CP_COMMIT();
#pragma unroll
    for (int it = 0; it < 16; it++) {
        int i = tid + 256 * it, r = i >> 5, cc = i & 31;
        CP16F(sb + SM_X1 + tile_off(r, cc), xsrc + ((size_t)(128 + r) * 32 + cc) * 16);
    }
    CP_COMMIT();

    // fused W normalization -> fp16: 2 threads per row (halves), 2-pass via L1
    {
        int r = tid >> 1, h = tid & 1;
        int cg = cbase + r;
        bool ok = (cg < C);
        const float4* wrow =
            (const float4*)(W + (size_t)(ok ? cg : cbase) * DD) + h * 32;
        float ss = 0.f;
#pragma unroll
        for (int i = 0; i < 32; i++) {
            float4 v = wrow[i];
            ss += v.x * v.x + v.y * v.y + v.z * v.z + v.w * v.w;
        }
        ss += __shfl_xor_sync(0xffffffffu, ss, 1);
        float inv = ok ? rsqrtf(ss) : 0.f;
#pragma unroll
        for (int i = 0; i < 16; i++) {
            float4 a = wrow[2 * i];        // L1 hit
            float4 d = wrow[2 * i + 1];
            uint4 u;
            u.x = pack_h2(a.x * inv, a.y * inv);
            u.y = pack_h2(a.z * inv, a.w * inv);
            u.z = pack_h2(d.x * inv, d.y * inv);
            u.w = pack_h2(d.z * inv, d.w * inv);
            *(uint4*)(smem + SM_W + tile_off(r, h * 16 + i)) = u;
        }
    }
    CP_WAIT1();        // X0 resident; X1 in flight
    __syncthreads();

    const int wm = wid & 3, wn = wid >> 2;
    const int m0 = wm * 32, n0 = wn * 64;
    const int a_rl   = ((lane >> 3) & 1) * 8 + (lane & 7);
    const int a_cchi = (lane >> 4) & 1;
    const int b_rl   = ((lane >> 4) & 1) * 8 + (lane & 7);
    const int b_cchi = (lane >> 3) & 1;
    const uint32_t wa = sb + SM_W;

    for (int b = 0; b < 4; b++) {
        const uint32_t xa = sb + ((b & 1) ? SM_X1 : SM_X0);

        uint32_t acc[2][8][2];   // fp16x2 accumulators
#pragma unroll
        for (int i = 0; i < 2; i++)
#pragma unroll
            for (int j = 0; j < 8; j++) {
                acc[i][j][0] = 0u;
                acc[i][j][1] = 0u;
            }

#pragma unroll
        for (int s = 0; s < 16; s++) {
            uint32_t afr[2][4];
#pragma unroll
            for (int i = 0; i < 2; i++) {
                int r = m0 + 16 * i + a_rl, cc = 2 * s + a_cchi;
                LDSM4(afr[i][0], afr[i][1], afr[i][2], afr[i][3],
                      xa + tile_off(r, cc));
            }
            uint32_t bfr[4][4];
#pragma unroll
            for (int j4 = 0; j4 < 4; j4++) {
                int r = n0 + 16 * j4 + b_rl, cc = 2 * s + b_cchi;
                LDSM4(bfr[j4][0], bfr[j4][1], bfr[j4][2], bfr[j4][3],
                      wa + tile_off(r, cc));
            }
#pragma unroll
            for (int j = 0; j < 8; j++) {
                uint32_t b0 = bfr[j >> 1][(j & 1) * 2];
                uint32_t b1 = bfr[j >> 1][(j & 1) * 2 + 1];
                mma16816h(acc[0][j], afr[0], b0, b1);
                mma16816h(acc[1][j], afr[1], b0, b1);
            }
        }

        // epilogue: unpack fp16 pairs, exp2, per-row reduce
        float rs[4] = {0.f, 0.f, 0.f, 0.f};
#pragma unroll
        for (int i = 0; i < 2; i++)
#pragma unroll
            for (int j = 0; j < 8; j++) {
                float2 c0 = h2_to_f2(acc[i][j][0]);   // row g,   cols 2t,2t+1
                float2 c1 = h2_to_f2(acc[i][j][1]);   // row g+8
                rs[2 * i]     += exp2f(fmaf(EXPC, c0.x, -EXPC))
                               + exp2f(fmaf(EXPC, c0.y, -EXPC));
                rs[2 * i + 1] += exp2f(fmaf(EXPC, c1.x, -EXPC))
                               + exp2f(fmaf(EXPC, c1.y, -EXPC));
            }
#pragma unroll
        for (int q = 0; q < 4; q++) {
            rs[q] += __shfl_xor_sync(0xffffffffu, rs[q], 1);
            rs[q] += __shfl_xor_sync(0xffffffffu, rs[q], 2);
        }
        if ((lane & 3) == 0) {
            int rbase = b * 128 + m0 + (lane >> 2);
#pragma unroll
            for (int q = 0; q < 4; q++)
                atomicAdd(&g_sumexp[rbase + 8 * q], rs[q]);
        }

        __syncthreads();   // everyone done reading buf[b&1]
        if (b < 2) {
            uint32_t dst = sb + ((b & 1) ? SM_X1 : SM_X0);
#pragma unroll
            for (int it = 0; it < 16; it++) {
                int i = tid + 256 * it, r = i >> 5, cc = i & 31;
                CP16F(dst + tile_off(r, cc),
                      xsrc + ((size_t)((b + 2) * 128 + r) * 32 + cc) * 16);
            }
            CP_COMMIT();
            CP_WAIT1();
        } else if (b == 2) {
            CP_WAIT0();
        }
        __syncthreads();
    }
}

// ---------------------------------------------------------
// finalize: pad removal, margin correction (exact cosine), lse, mean
__global__ void finalize_kernel(float* __restrict__ out, int npad) {
    __shared__ double sd[BB];
    int b = threadIdx.x;
    float ct = g_cost[b];
    float lt = S_SCALE * (ct - MARGIN);
    float s = g_sumexp[b] - (float)npad * expf(-30.0f)
            + __expf(lt - 30.0f) - __expf(S_SCALE * ct - 30.0f);
    float nll = 30.0f + logf(s) - lt;
    sd[b] = (double)nll;
    __syncthreads();
    for (int o = 256; o; o >>= 1) {
        if (b < o) sd[b] += sd[b + o];
        __syncthreads();
    }
    if (b == 0) out[0] = (float)(sd[0] / (double)BB);
}

// ---------------------------------------------------------
extern "C" void kernel_launch(void* const* d_in, const int* in_sizes, int n_in,
                              void* d_out, int out_size) {
    const float* inputs  = (const float*)d_in[0];
    const float* weight  = (const float*)d_in[1];
    const int*   targets = (const int*)d_in[2];
    float* out = (float*)d_out;

    int C = in_sizes[1] / DD;
    int gridC = (C + 127) / 128;
    int npad = gridC * 128 - C;

    cudaFuncSetAttribute(gemm_sumexp_kernel,
                         cudaFuncAttributeMaxDynamicSharedMemorySize, SM_TOTAL);

    prep_norm_kernel<<<BB / 8, 256>>>(inputs, targets);
    cost_kernel<<<BB / 8, 256>>>(weight, inputs);
    gemm_sumexp_kernel<<<gridC, 256, SM_TOTAL>>>(weight, C);
    finalize_kernel<<<1, BB>>>(out, npad);
}